// round 10
// baseline (speedup 1.0000x reference)
#include <cuda_runtime.h>
#include <cuda_fp16.h>
#include <cstdint>

// Problem constants: N=4096, D=128, S=32768, NUM_CLASS=500000.
#define DIM 128
#define MAX_S 32768
#define MAX_N 4096
#define NUM_CLASS_MAX 500000

// Scratch: fp16 operands + gathered fp32 bias.
static __device__ __half g_w[(size_t)MAX_S * DIM];
static __device__ __half g_x[(size_t)MAX_N * DIM];
static __device__ float g_bias[MAX_S];
static __device__ int g_ids_is64;

// ---------------------------------------------------------------------------
// Kernel 0: detect sample_ids dtype (int32 vs int64).
// ---------------------------------------------------------------------------
__global__ void detect_ids_kernel(const void* __restrict__ ids, int S) {
    __shared__ int ok;
    if (threadIdx.x == 0) ok = 1;
    __syncthreads();
    const long long* p = (const long long*)ids;
    int n64 = S / 2;
    for (int s = threadIdx.x; s < n64; s += blockDim.x) {
        long long v = p[s];
        if (v < 0 || v >= NUM_CLASS_MAX) ok = 0;
    }
    __syncthreads();
    if (threadIdx.x == 0) g_ids_is64 = ok;
}

__device__ __forceinline__ long long read_id(const void* ids, int s) {
    long long id = g_ids_is64 ? ((const long long*)ids)[s]
                              : (long long)((const int*)ids)[s];
    if (id < 0 || id >= NUM_CLASS_MAX) id = 0;
    return id;
}

// ---------------------------------------------------------------------------
// Kernel 1: gather weight[ids] -> g_w (fp16), bias[ids] -> g_bias.
// ---------------------------------------------------------------------------
__global__ void gather_kernel(const float* __restrict__ w,
                              const float* __restrict__ bias,
                              const void* __restrict__ ids,
                              int S) {
    int warp = (blockIdx.x * blockDim.x + threadIdx.x) >> 5;
    int lane = threadIdx.x & 31;
    int nwarps = (gridDim.x * blockDim.x) >> 5;
    for (int s = warp; s < S; s += nwarps) {
        long long id = read_id(ids, s);
        float4 v = ((const float4*)(w + (size_t)id * DIM))[lane];
        __half2 h0 = __float22half2_rn(make_float2(v.x, v.y));
        __half2 h1 = __float22half2_rn(make_float2(v.z, v.w));
        __half2* dst = (__half2*)(g_w + (size_t)s * DIM) + lane * 2;
        dst[0] = h0;
        dst[1] = h1;
        if (lane == 0) g_bias[s] = bias[id];
    }
}

// ---------------------------------------------------------------------------
// Kernel 1b: convert x -> g_x (fp16).
// ---------------------------------------------------------------------------
__global__ void convert_x_kernel(const float* __restrict__ x, int total_f4) {
    int i = blockIdx.x * blockDim.x + threadIdx.x;
    int stride = gridDim.x * blockDim.x;
    for (; i < total_f4; i += stride) {
        float4 v = ((const float4*)x)[i];
        __half2 h0 = __float22half2_rn(make_float2(v.x, v.y));
        __half2 h1 = __float22half2_rn(make_float2(v.z, v.w));
        __half2* dst = (__half2*)g_x + i * 2;
        dst[0] = h0;
        dst[1] = h1;
    }
}

// ---------------------------------------------------------------------------
// Kernel 2: fp16 GEMM via mma.m16n8k16 + ldmatrix fragment loads.
// BM=128, BN=128, 256 threads (8 warps, 2x4), warp tile 64x32, 2 CTAs/SM.
// Single 64KB buffer: A[128][256B] + B[128][256B] (full K=128 per row),
// XOR-8 16B-block swizzle. cp.async in 4 K-quarter commit groups (16KB each),
// progressively drained so MMAs start after the first 16KB lands and the
// two resident CTAs interleave load/compute at fine grain.
// ---------------------------------------------------------------------------
#define BM 128
#define BN 128
#define A_BYTES (BM * DIM * 2)      // 32768
#define B_BYTES (BN * DIM * 2)      // 32768
#define SM_TOTAL (A_BYTES + B_BYTES) // 65536
#define NGROUP 4                     // K-quarter commit groups

__device__ __forceinline__ void mma_f16(float c[4], const uint32_t a[4],
                                        const uint32_t b[2]) {
    asm volatile(
        "mma.sync.aligned.m16n8k16.row.col.f32.f16.f16.f32 "
        "{%0,%1,%2,%3}, {%4,%5,%6,%7}, {%8,%9}, {%0,%1,%2,%3};\n"
        : "+f"(c[0]), "+f"(c[1]), "+f"(c[2]), "+f"(c[3])
        : "r"(a[0]), "r"(a[1]), "r"(a[2]), "r"(a[3]), "r"(b[0]), "r"(b[1]));
}

__device__ __forceinline__ void ldsm_x4(uint32_t* r, uint32_t addr) {
    asm volatile(
        "ldmatrix.sync.aligned.m8n8.x4.shared.b16 {%0,%1,%2,%3}, [%4];"
        : "=r"(r[0]), "=r"(r[1]), "=r"(r[2]), "=r"(r[3]) : "r"(addr));
}

__device__ __forceinline__ void cp_async16(uint32_t smem_addr, const void* gptr) {
    asm volatile("cp.async.cg.shared.global [%0], [%1], 16;\n"
                 :: "r"(smem_addr), "l"(gptr));
}
__device__ __forceinline__ void cp_commit() {
    asm volatile("cp.async.commit_group;\n");
}
__device__ __forceinline__ void st_cs_f2(float* p, float a, float b) {
    asm volatile("st.global.cs.v2.f32 [%0], {%1,%2};\n"
                 :: "l"(p), "f"(a), "f"(b) : "memory");
}

__global__ __launch_bounds__(256, 2)
void gemm_f16_kernel(float* __restrict__ out, int N, int S) {
    extern __shared__ char sm[];
    const int tid  = threadIdx.x;
    const int lane = tid & 31;
    const int wid  = tid >> 5;
    const int wm   = wid & 1;        // 2 warp rows of 64
    const int wn   = wid >> 1;       // 4 warp cols of 32
    const int gid  = lane >> 2;      // 0..7
    const int tg   = lane & 3;       // 0..3

    const int m0 = blockIdx.x * BM;  // x = M tiles -> consecutive CTAs share B
    const int n0 = blockIdx.y * BN;

    uint32_t sbase;
    asm("{ .reg .u64 t; cvta.to.shared.u64 t, %1; cvt.u32.u64 %0, t; }"
        : "=r"(sbase) : "l"(sm));
    const uint32_t Ab = sbase;
    const uint32_t Bb = sbase + A_BYTES;

    // ---- prefetch: 4 K-quarter commit groups (A 8KB + B 8KB each) ----
#pragma unroll
    for (int g = 0; g < NGROUP; g++) {
#pragma unroll
        for (int i = 0; i < 2; i++) {       // A: 128 rows x 4 blocks = 512 ops
            int f = tid + i * 256;
            int r = f >> 2, qq = f & 3;
            int q = g * 4 + qq;             // 16B block index 0..15
            uint32_t dst = Ab + (uint32_t)(r * 256 + ((q ^ (r & 7)) << 4));
            cp_async16(dst, g_x + (size_t)(m0 + r) * DIM + q * 8);
        }
#pragma unroll
        for (int i = 0; i < 2; i++) {       // B: 128 rows x 4 blocks = 512 ops
            int f = tid + i * 256;
            int r = f >> 2, qq = f & 3;
            int q = g * 4 + qq;
            uint32_t dst = Bb + (uint32_t)(r * 256 + ((q ^ (r & 7)) << 4));
            cp_async16(dst, g_w + (size_t)(n0 + r) * DIM + q * 8);
        }
        cp_commit();
    }

    float c[4][4][4];
#pragma unroll
    for (int mi = 0; mi < 4; mi++)
#pragma unroll
        for (int ni = 0; ni < 4; ni++)
#pragma unroll
            for (int j = 0; j < 4; j++) c[mi][ni][j] = 0.0f;

    // ---- ldmatrix per-lane row assignments (proven in rounds 8-9) ----
    const int rowA = (lane & 15);
    const int selA = (lane >> 4) & 1;
    const int rowB = (lane & 7) + ((lane & 16) >> 1);
    const int selB = (lane >> 3) & 1;
    const int swzA = rowA & 7;
    const int swzB = rowB & 7;

    // Fragment base addresses are loop-invariant (single buffer).
    uint32_t aAddr[4], bAddr[2];
#pragma unroll
    for (int mi = 0; mi < 4; mi++)
        aAddr[mi] = Ab + (uint32_t)((wm * 64 + mi * 16 + rowA) * 256);
#pragma unroll
    for (int nj = 0; nj < 2; nj++)
        bAddr[nj] = Bb + (uint32_t)((wn * 32 + nj * 16 + rowB) * 256);

    // ---- compute: 2 k16-steps per group, drain groups progressively ----
#pragma unroll
    for (int g = 0; g < NGROUP; g++) {
        switch (NGROUP - 1 - g) {
            case 3: asm volatile("cp.async.wait_group 3;\n"); break;
            case 2: asm volatile("cp.async.wait_group 2;\n"); break;
            case 1: asm volatile("cp.async.wait_group 1;\n"); break;
            default: asm volatile("cp.async.wait_group 0;\n"); break;
        }
        __syncthreads();
#pragma unroll
        for (int k2 = 0; k2 < 2; k2++) {
            const int ks = g * 2 + k2;                 // 0..7
            const uint32_t offA = (uint32_t)(((2 * ks + selA) ^ swzA) << 4);
            const uint32_t offB = (uint32_t)(((2 * ks + selB) ^ swzB) << 4);
            uint32_t a[4][4], b[2][4];
#pragma unroll
            for (int mi = 0; mi < 4; mi++)
                ldsm_x4(a[mi], aAddr[mi] + offA);
#pragma unroll
            for (int nj = 0; nj < 2; nj++)
                ldsm_x4(b[nj], bAddr[nj] + offB);
#pragma unroll
            for (int mi = 0; mi < 4; mi++) {
#pragma unroll
                for (int ni = 0; ni < 4; ni++)
                    mma_f16(c[mi][ni], a[mi], &b[ni >> 1][(ni & 1) * 2]);
            }
        }
    }

    // ---- epilogue: bias add + streaming (.cs) float2 stores ----
#pragma unroll
    for (int mi = 0; mi < 4; mi++) {
        int r0 = m0 + wm * 64 + mi * 16 + gid;
#pragma unroll
        for (int ni = 0; ni < 4; ni++) {
            int col = n0 + wn * 32 + ni * 8 + 2 * tg;
            float b0 = g_bias[col];
            float b1 = g_bias[col + 1];
            st_cs_f2(out + (size_t)r0 * S + col,
                     c[mi][ni][0] + b0, c[mi][ni][1] + b1);
            st_cs_f2(out + (size_t)(r0 + 8) * S + col,
                     c[mi][ni][2] + b0, c[mi][ni][3] + b1);
        }
    }
}

// ---------------------------------------------------------------------------
// Kernel 3: pass-through sample_ids after the logits block.
// ---------------------------------------------------------------------------
__global__ void write_ids_kernel(const void* __restrict__ ids, void* out,
                                 long long base, long long extra, int S) {
    int s = blockIdx.x * blockDim.x + threadIdx.x;
    if (s >= S) return;
    long long id = read_id(ids, s);
    if (extra >= 2LL * S) {
        long long* p = (long long*)((float*)out + base);
        p[s] = id;
    } else if (extra >= (long long)S) {
        ((float*)out)[base + s] = (float)id;
    }
}

// ---------------------------------------------------------------------------
extern "C" void kernel_launch(void* const* d_in, const int* in_sizes, int n_in,
                              void* d_out, int out_size) {
    const float* x    = (const float*)d_in[0];
    const float* w    = (const float*)d_in[1];
    const float* bias = (const float*)d_in[2];
    const void*  ids  = d_in[3];

    const int N = in_sizes[0] / DIM;   // 4096
    const int S = in_sizes[3];         // 32768

    detect_ids_kernel<<<1, 256>>>(ids, S);
    gather_kernel<<<256, 256>>>(w, bias, ids, S);
    convert_x_kernel<<<128, 256>>>(x, N * (DIM / 4));

    static int smem_set = 0;
    if (!smem_set) {
        cudaFuncSetAttribute(gemm_f16_kernel,
                             cudaFuncAttributeMaxDynamicSharedMemorySize,
                             SM_TOTAL);
        smem_set = 1;
    }
    dim3 grid(N / BM, S / BN);
    gemm_f16_kernel<<<grid, 256, SM_TOTAL>>>((float*)d_out, N, S);

    long long base  = (long long)N * (long long)S;
    long long extra = (long long)out_size - base;
    if (extra > 0) {
        write_ids_kernel<<<(S + 255) / 256, 256>>>(ids, d_out, base, extra, S);
    }
}

// round 11
// speedup vs baseline: 1.0481x; 1.0481x over previous
#include <cuda_runtime.h>
#include <cuda_fp16.h>
#include <cstdint>

// Problem constants: N=4096, D=128, S=32768, NUM_CLASS=500000.
#define DIM 128
#define MAX_S 32768
#define MAX_N 4096
#define NUM_CLASS_MAX 500000

// Scratch: fp16 operands + gathered fp32 bias.
static __device__ __half g_w[(size_t)MAX_S * DIM];
static __device__ __half g_x[(size_t)MAX_N * DIM];
static __device__ float g_bias[MAX_S];
static __device__ int g_ids_is64;

// ---------------------------------------------------------------------------
// Kernel 0: detect sample_ids dtype (int32 vs int64).
// ---------------------------------------------------------------------------
__global__ void detect_ids_kernel(const void* __restrict__ ids, int S) {
    __shared__ int ok;
    if (threadIdx.x == 0) ok = 1;
    __syncthreads();
    const long long* p = (const long long*)ids;
    int n64 = S / 2;
    for (int s = threadIdx.x; s < n64; s += blockDim.x) {
        long long v = p[s];
        if (v < 0 || v >= NUM_CLASS_MAX) ok = 0;
    }
    __syncthreads();
    if (threadIdx.x == 0) g_ids_is64 = ok;
}

__device__ __forceinline__ long long read_id(const void* ids, int s) {
    long long id = g_ids_is64 ? ((const long long*)ids)[s]
                              : (long long)((const int*)ids)[s];
    if (id < 0 || id >= NUM_CLASS_MAX) id = 0;
    return id;
}

// ---------------------------------------------------------------------------
// Kernel 1: gather weight[ids] -> g_w (fp16), bias[ids] -> g_bias.
// ---------------------------------------------------------------------------
__global__ void gather_kernel(const float* __restrict__ w,
                              const float* __restrict__ bias,
                              const void* __restrict__ ids,
                              int S) {
    int warp = (blockIdx.x * blockDim.x + threadIdx.x) >> 5;
    int lane = threadIdx.x & 31;
    int nwarps = (gridDim.x * blockDim.x) >> 5;
    for (int s = warp; s < S; s += nwarps) {
        long long id = read_id(ids, s);
        float4 v = ((const float4*)(w + (size_t)id * DIM))[lane];
        __half2 h0 = __float22half2_rn(make_float2(v.x, v.y));
        __half2 h1 = __float22half2_rn(make_float2(v.z, v.w));
        __half2* dst = (__half2*)(g_w + (size_t)s * DIM) + lane * 2;
        dst[0] = h0;
        dst[1] = h1;
        if (lane == 0) g_bias[s] = bias[id];
    }
}

// ---------------------------------------------------------------------------
// Kernel 1b: convert x -> g_x (fp16).
// ---------------------------------------------------------------------------
__global__ void convert_x_kernel(const float* __restrict__ x, int total_f4) {
    int i = blockIdx.x * blockDim.x + threadIdx.x;
    int stride = gridDim.x * blockDim.x;
    for (; i < total_f4; i += stride) {
        float4 v = ((const float4*)x)[i];
        __half2 h0 = __float22half2_rn(make_float2(v.x, v.y));
        __half2 h1 = __float22half2_rn(make_float2(v.z, v.w));
        __half2* dst = (__half2*)g_x + i * 2;
        dst[0] = h0;
        dst[1] = h1;
    }
}

// ---------------------------------------------------------------------------
// Kernel 2: fp16 GEMM via mma.m16n8k16 + ldmatrix fragment loads.
// BM=64, BN=128, 128 threads (4 warps, 1x4), warp tile 64x32 -> 4 CTAs/SM
// (regs 128*128*4 = 64K RF, smem 48KB*4 = 192KB). Four independent CTAs per
// SM interleave prolog/mainloop/epilogue phases.
// Rows hold full K=128 (256B); XOR-8 16B-block swizzle. cp.async in 2 K-half
// commit groups (128B/row each -> full L2 lines), progressively drained.
// ---------------------------------------------------------------------------
#define BM 64
#define BN 128
#define A_BYTES (BM * DIM * 2)       // 16384
#define B_BYTES (BN * DIM * 2)       // 32768
#define SM_TOTAL (A_BYTES + B_BYTES) // 49152
#define NGROUP 2                     // K-half commit groups

__device__ __forceinline__ void mma_f16(float c[4], const uint32_t a[4],
                                        const uint32_t b[2]) {
    asm volatile(
        "mma.sync.aligned.m16n8k16.row.col.f32.f16.f16.f32 "
        "{%0,%1,%2,%3}, {%4,%5,%6,%7}, {%8,%9}, {%0,%1,%2,%3};\n"
        : "+f"(c[0]), "+f"(c[1]), "+f"(c[2]), "+f"(c[3])
        : "r"(a[0]), "r"(a[1]), "r"(a[2]), "r"(a[3]), "r"(b[0]), "r"(b[1]));
}

__device__ __forceinline__ void ldsm_x4(uint32_t* r, uint32_t addr) {
    asm volatile(
        "ldmatrix.sync.aligned.m8n8.x4.shared.b16 {%0,%1,%2,%3}, [%4];"
        : "=r"(r[0]), "=r"(r[1]), "=r"(r[2]), "=r"(r[3]) : "r"(addr));
}

__device__ __forceinline__ void cp_async16(uint32_t smem_addr, const void* gptr) {
    asm volatile("cp.async.cg.shared.global [%0], [%1], 16;\n"
                 :: "r"(smem_addr), "l"(gptr));
}
__device__ __forceinline__ void cp_commit() {
    asm volatile("cp.async.commit_group;\n");
}
__device__ __forceinline__ void st_cs_f2(float* p, float a, float b) {
    asm volatile("st.global.cs.v2.f32 [%0], {%1,%2};\n"
                 :: "l"(p), "f"(a), "f"(b) : "memory");
}

__global__ __launch_bounds__(128, 4)
void gemm_f16_kernel(float* __restrict__ out, int N, int S) {
    extern __shared__ char sm[];
    const int tid  = threadIdx.x;
    const int lane = tid & 31;
    const int wid  = tid >> 5;       // 0..3 = warp col (warp tile 64x32)
    const int wn   = wid;
    const int gid  = lane >> 2;      // 0..7
    const int tg   = lane & 3;       // 0..3

    const int m0 = blockIdx.x * BM;  // x = M tiles -> consecutive CTAs share B
    const int n0 = blockIdx.y * BN;

    uint32_t sbase;
    asm("{ .reg .u64 t; cvta.to.shared.u64 t, %1; cvt.u32.u64 %0, t; }"
        : "=r"(sbase) : "l"(sm));
    const uint32_t Ab = sbase;
    const uint32_t Bb = sbase + A_BYTES;

    // ---- prefetch: 2 K-half commit groups (A 8KB + B 16KB each) ----
#pragma unroll
    for (int g = 0; g < NGROUP; g++) {
#pragma unroll
        for (int i = 0; i < 4; i++) {       // A: 64 rows x 8 blocks = 512 ops
            int f = tid + i * 128;
            int r = f >> 3, q8 = f & 7;
            int q = g * 8 + q8;             // 16B block index 0..15
            uint32_t dst = Ab + (uint32_t)(r * 256 + ((q ^ (r & 7)) << 4));
            cp_async16(dst, g_x + (size_t)(m0 + r) * DIM + q * 8);
        }
#pragma unroll
        for (int i = 0; i < 8; i++) {       // B: 128 rows x 8 blocks = 1024 ops
            int f = tid + i * 128;
            int r = f >> 3, q8 = f & 7;
            int q = g * 8 + q8;
            uint32_t dst = Bb + (uint32_t)(r * 256 + ((q ^ (r & 7)) << 4));
            cp_async16(dst, g_w + (size_t)(n0 + r) * DIM + q * 8);
        }
        cp_commit();
    }

    float c[4][4][4];
#pragma unroll
    for (int mi = 0; mi < 4; mi++)
#pragma unroll
        for (int ni = 0; ni < 4; ni++)
#pragma unroll
            for (int j = 0; j < 4; j++) c[mi][ni][j] = 0.0f;

    // ---- ldmatrix per-lane row assignments (proven rounds 8-10) ----
    const int rowA = (lane & 15);
    const int selA = (lane >> 4) & 1;
    const int rowB = (lane & 7) + ((lane & 16) >> 1);
    const int selB = (lane >> 3) & 1;
    const int swzA = rowA & 7;
    const int swzB = rowB & 7;

    // Fragment base addresses are loop-invariant (single buffer).
    uint32_t aAddr[4], bAddr[2];
#pragma unroll
    for (int mi = 0; mi < 4; mi++)
        aAddr[mi] = Ab + (uint32_t)((mi * 16 + rowA) * 256);
#pragma unroll
    for (int nj = 0; nj < 2; nj++)
        bAddr[nj] = Bb + (uint32_t)((wn * 32 + nj * 16 + rowB) * 256);

    // ---- compute: 4 k16-steps per K-half, drain groups progressively ----
#pragma unroll
    for (int g = 0; g < NGROUP; g++) {
        if (g == 0) asm volatile("cp.async.wait_group 1;\n");
        else        asm volatile("cp.async.wait_group 0;\n");
        __syncthreads();
#pragma unroll
        for (int k2 = 0; k2 < 4; k2++) {
            const int ks = g * 4 + k2;                 // 0..7
            const uint32_t offA = (uint32_t)(((2 * ks + selA) ^ swzA) << 4);
            const uint32_t offB = (uint32_t)(((2 * ks + selB) ^ swzB) << 4);
            uint32_t a[4][4], b[2][4];
#pragma unroll
            for (int mi = 0; mi < 4; mi++)
                ldsm_x4(a[mi], aAddr[mi] + offA);
#pragma unroll
            for (int nj = 0; nj < 2; nj++)
                ldsm_x4(b[nj], bAddr[nj] + offB);
#pragma unroll
            for (int mi = 0; mi < 4; mi++) {
#pragma unroll
                for (int ni = 0; ni < 4; ni++)
                    mma_f16(c[mi][ni], a[mi], &b[ni >> 1][(ni & 1) * 2]);
            }
        }
    }

    // ---- epilogue: bias add + streaming (.cs) float2 stores ----
#pragma unroll
    for (int mi = 0; mi < 4; mi++) {
        int r0 = m0 + mi * 16 + gid;
#pragma unroll
        for (int ni = 0; ni < 4; ni++) {
            int col = n0 + wn * 32 + ni * 8 + 2 * tg;
            float b0 = g_bias[col];
            float b1 = g_bias[col + 1];
            st_cs_f2(out + (size_t)r0 * S + col,
                     c[mi][ni][0] + b0, c[mi][ni][1] + b1);
            st_cs_f2(out + (size_t)(r0 + 8) * S + col,
                     c[mi][ni][2] + b0, c[mi][ni][3] + b1);
        }
    }
}

// ---------------------------------------------------------------------------
// Kernel 3: pass-through sample_ids after the logits block.
// ---------------------------------------------------------------------------
__global__ void write_ids_kernel(const void* __restrict__ ids, void* out,
                                 long long base, long long extra, int S) {
    int s = blockIdx.x * blockDim.x + threadIdx.x;
    if (s >= S) return;
    long long id = read_id(ids, s);
    if (extra >= 2LL * S) {
        long long* p = (long long*)((float*)out + base);
        p[s] = id;
    } else if (extra >= (long long)S) {
        ((float*)out)[base + s] = (float)id;
    }
}

// ---------------------------------------------------------------------------
extern "C" void kernel_launch(void* const* d_in, const int* in_sizes, int n_in,
                              void* d_out, int out_size) {
    const float* x    = (const float*)d_in[0];
    const float* w    = (const float*)d_in[1];
    const float* bias = (const float*)d_in[2];
    const void*  ids  = d_in[3];

    const int N = in_sizes[0] / DIM;   // 4096
    const int S = in_sizes[3];         // 32768

    detect_ids_kernel<<<1, 256>>>(ids, S);
    gather_kernel<<<256, 256>>>(w, bias, ids, S);
    convert_x_kernel<<<128, 256>>>(x, N * (DIM / 4));

    static int smem_set = 0;
    if (!smem_set) {
        cudaFuncSetAttribute(gemm_f16_kernel,
                             cudaFuncAttributeMaxDynamicSharedMemorySize,
                             SM_TOTAL);
        smem_set = 1;
    }
    dim3 grid(N / BM, S / BN);
    gemm_f16_kernel<<<grid, 128, SM_TOTAL>>>((float*)d_out, N, S);

    long long base  = (long long)N * (long long)S;
    long long extra = (long long)out_size - base;
    if (extra > 0) {
        write_ids_kernel<<<(S + 255) / 256, 256>>>(ids, d_out, base, extra, S);
    }
}